// round 1
// baseline (speedup 1.0000x reference)
#include <cuda_runtime.h>
#include <cstdint>

#define NN 50000
#define EE 800000
#define GG 64
#define FF 64
#define BN_EPS 1e-5f

// ---------------- scratch (static device globals; no runtime allocation) ---
__device__ float d_h[(size_t)NN * FF];     // GEMM output / scatter source
__device__ float d_y[(size_t)NN * FF];     // aggregation output / GEMM input
__device__ float d_s[NN];                  // layer-1 scalar aggregate
__device__ float d_deg[NN];
__device__ float d_dinv[NN];
__device__ float d_norm[EE];
__device__ float d_ssum[2];                // scalar sum / sumsq
__device__ float d_fsum[3][FF];            // per-feature sums, layers 2..4
__device__ float d_fsq[3][FF];
__device__ float d_pooled[GG * FF];
__device__ float d_cnt[GG];
__device__ float d_aff_a[4][FF];           // fused BN affine: z = relu(a*y + c)
__device__ float d_aff_c[4][FF];

// ---------------- helpers ---------------------------------------------------
__device__ __forceinline__ void red_add_v4(float* p, float4 v) {
    asm volatile("red.global.add.v4.f32 [%0], {%1,%2,%3,%4};"
                 :: "l"(p), "f"(v.x), "f"(v.y), "f"(v.z), "f"(v.w) : "memory");
}

// ---------------- setup kernels --------------------------------------------
__global__ void k_zero() {
    int t = blockIdx.x * blockDim.x + threadIdx.x;
    if (t < 2) d_ssum[t] = 0.f;
    if (t < 3 * FF) { ((float*)d_fsum)[t] = 0.f; ((float*)d_fsq)[t] = 0.f; }
    if (t < GG * FF) d_pooled[t] = 0.f;
    if (t < GG) d_cnt[t] = 0.f;
}

__global__ void k_init_deg() {
    int n = blockIdx.x * blockDim.x + threadIdx.x;
    if (n < NN) d_deg[n] = 1.0f;   // self-loop
}

__global__ void k_deg(const int* __restrict__ ei, int E_) {
    int e = blockIdx.x * blockDim.x + threadIdx.x;
    if (e < E_) atomicAdd(&d_deg[ei[E_ + e]], 1.0f);
}

// dinv = deg^-0.5 ; init s with self-loop contribution x * dinv^2
__global__ void k_dinv(const float* __restrict__ x) {
    int n = blockIdx.x * blockDim.x + threadIdx.x;
    if (n >= NN) return;
    float di = rsqrtf(d_deg[n]);
    d_dinv[n] = di;
    d_s[n] = x[n] * di * di;
}

// per-edge norm, plus layer-1 scalar scatter: s[col] += x[row]*norm
__global__ void k_norm_s1(const int* __restrict__ ei, const float* __restrict__ x, int E_) {
    int e = blockIdx.x * blockDim.x + threadIdx.x;
    if (e >= E_) return;
    int r = ei[e], c = ei[E_ + e];
    float nm = d_dinv[r] * d_dinv[c];
    d_norm[e] = nm;
    atomicAdd(&d_s[c], x[r] * nm);
}

// ---------------- statistics -----------------------------------------------
__global__ void k_stats_s() {
    float s = 0.f, q = 0.f;
    for (int n = blockIdx.x * blockDim.x + threadIdx.x; n < NN; n += gridDim.x * blockDim.x) {
        float v = d_s[n];
        s += v; q += v * v;
    }
    for (int o = 16; o; o >>= 1) {
        s += __shfl_down_sync(0xffffffffu, s, o);
        q += __shfl_down_sync(0xffffffffu, q, o);
    }
    __shared__ float sh[2][8];
    int w = threadIdx.x >> 5;
    if ((threadIdx.x & 31) == 0) { sh[0][w] = s; sh[1][w] = q; }
    __syncthreads();
    if (threadIdx.x == 0) {
        s = 0.f; q = 0.f;
        for (int i = 0; i < 8; i++) { s += sh[0][i]; q += sh[1][i]; }
        atomicAdd(&d_ssum[0], s);
        atomicAdd(&d_ssum[1], q);
    }
}

// affine for layer 1: y1[n,f] = s[n]*W1[f]; BN over f -> a*s + c
__global__ void k_fin1(const float* __restrict__ W1, const float* __restrict__ g1,
                       const float* __restrict__ bt1) {
    int f = threadIdx.x;
    if (f >= FF) return;
    float inv_n = 1.0f / (float)NN;
    float mean_s = d_ssum[0] * inv_n;
    float var_s  = d_ssum[1] * inv_n - mean_s * mean_s;
    float w = W1[f];
    float ia = g1[f] * rsqrtf(var_s * w * w + BN_EPS);
    float A = ia * w;
    d_aff_a[0][f] = A;
    d_aff_c[0][f] = bt1[f] - A * mean_s;
}

// column sum/sumsq of d_y -> d_fsum[L], d_fsq[L]
__global__ void k_stats64(int L) {
    int t = threadIdx.x;
    int f = t & 63, rg = t >> 6;           // 4 row groups
    float s = 0.f, q = 0.f;
    for (int n = blockIdx.x * 4 + rg; n < NN; n += gridDim.x * 4) {
        float v = d_y[(size_t)n * FF + f];
        s += v; q += v * v;
    }
    __shared__ float shs[256], shq[256];
    shs[t] = s; shq[t] = q;
    __syncthreads();
    if (rg == 0) {
        s = shs[f] + shs[64 + f] + shs[128 + f] + shs[192 + f];
        q = shq[f] + shq[64 + f] + shq[128 + f] + shq[192 + f];
        atomicAdd(&d_fsum[L][f], s);
        atomicAdd(&d_fsq[L][f], q);
    }
}

__global__ void k_fin64(int L, const float* __restrict__ g, const float* __restrict__ bt) {
    int f = threadIdx.x;
    if (f >= FF) return;
    float inv_n = 1.0f / (float)NN;
    float mean = d_fsum[L][f] * inv_n;
    float var  = d_fsq[L][f] * inv_n - mean * mean;
    float ia = g[f] * rsqrtf(var + BN_EPS);
    d_aff_a[L + 1][f] = ia;
    d_aff_c[L + 1][f] = bt[f] - ia * mean;
}

// ---------------- GEMM: d_h = relu(affine(src)) @ W -------------------------
// 64x64 tile per block, 256 threads, thread computes 4x4 micro-tile.
template <bool FROM_S>
__global__ void k_gemm(int L, const float* __restrict__ W) {
    __shared__ float Zs[FF][FF + 1];   // [k][localrow] (transposed)
    __shared__ float Ws[FF][FF];       // [k][col]
    __shared__ float sa[FF], sc[FF];
    int t = threadIdx.x;
    int base = blockIdx.x * FF;

    if (t < FF) { sa[t] = d_aff_a[L][t]; sc[t] = d_aff_c[L][t]; }
    __syncthreads();

    {   // copy W (4096 floats, linear, vectorized)
        const float4* W4 = (const float4*)W;
        float4* Ws4 = (float4*)&Ws[0][0];
        #pragma unroll
        for (int i = 0; i < 4; i++) Ws4[t + i * 256] = W4[t + i * 256];
    }

    int lr = t >> 2;               // 0..63 local row
    int cg = (t & 3) * 4;          // col group base
    int row = base + lr;
    if (FROM_S) {
        float sval = (row < NN) ? d_s[row] : 0.f;
        #pragma unroll
        for (int i = 0; i < 4; i++) {
            int cc = cg + i * 16;
            #pragma unroll
            for (int j = 0; j < 4; j++)
                Zs[cc + j][lr] = fmaxf(sa[cc + j] * sval + sc[cc + j], 0.f);
        }
    } else {
        #pragma unroll
        for (int i = 0; i < 4; i++) {
            int cc = cg + i * 16;
            float4 v = (row < NN) ? *(const float4*)(d_y + (size_t)row * FF + cc)
                                  : make_float4(0.f, 0.f, 0.f, 0.f);
            Zs[cc + 0][lr] = fmaxf(sa[cc + 0] * v.x + sc[cc + 0], 0.f);
            Zs[cc + 1][lr] = fmaxf(sa[cc + 1] * v.y + sc[cc + 1], 0.f);
            Zs[cc + 2][lr] = fmaxf(sa[cc + 2] * v.z + sc[cc + 2], 0.f);
            Zs[cc + 3][lr] = fmaxf(sa[cc + 3] * v.w + sc[cc + 3], 0.f);
        }
    }
    __syncthreads();

    int tx = t & 15, ty = t >> 4;
    float acc[4][4] = {};
    #pragma unroll 16
    for (int k = 0; k < FF; k++) {
        float zr[4], wc[4];
        #pragma unroll
        for (int r = 0; r < 4; r++) zr[r] = Zs[k][ty + 16 * r];
        #pragma unroll
        for (int j = 0; j < 4; j++) wc[j] = Ws[k][tx + 16 * j];
        #pragma unroll
        for (int r = 0; r < 4; r++)
            #pragma unroll
            for (int j = 0; j < 4; j++)
                acc[r][j] = fmaf(zr[r], wc[j], acc[r][j]);
    }
    #pragma unroll
    for (int r = 0; r < 4; r++) {
        int orow = base + ty + 16 * r;
        if (orow < NN) {
            #pragma unroll
            for (int j = 0; j < 4; j++)
                d_h[(size_t)orow * FF + tx + 16 * j] = acc[r][j];
        }
    }
}

// ---------------- aggregation ----------------------------------------------
// init y with self-loop: y[n] = h[n] * dinv[n]^2   (also serves as zero-init)
__global__ void k_selfloop() {
    int t = blockIdx.x * blockDim.x + threadIdx.x;
    int n = t >> 4, lane = t & 15;
    if (n >= NN) return;
    float d = d_dinv[n]; d = d * d;
    float4 v = ((const float4*)(d_h + (size_t)n * FF))[lane];
    v.x *= d; v.y *= d; v.z *= d; v.w *= d;
    ((float4*)(d_y + (size_t)n * FF))[lane] = v;
}

// y[col] += h[row] * norm   (16 threads/edge, vector RED)
__global__ void k_scatter(const int* __restrict__ ei, int E_) {
    int t = blockIdx.x * blockDim.x + threadIdx.x;
    int e = t >> 4, lane = t & 15;
    if (e >= E_) return;
    int r = ei[e], c = ei[E_ + e];
    float nm = d_norm[e];
    float4 v = __ldg((const float4*)(d_h + (size_t)r * FF) + lane);
    v.x *= nm; v.y *= nm; v.z *= nm; v.w *= nm;
    red_add_v4(d_y + (size_t)c * FF + lane * 4, v);
}

// ---------------- pooling + head -------------------------------------------
// batch is sorted: register-accumulate per graph, flush on change.
__global__ void k_pool(const int* __restrict__ batch) {
    int t = threadIdx.x;
    int f = t & 63, rg = t >> 6;
    int base = blockIdx.x * 256;
    float af = d_aff_a[3][f], cf = d_aff_c[3][f];
    float acc = 0.f, cacc = 0.f;
    int gcur = -1;
    for (int i = 0; i < 64; i++) {
        int n = base + rg + 4 * i;
        if (n >= NN) break;
        int g = batch[n];
        if (g != gcur) {
            if (gcur >= 0) {
                atomicAdd(&d_pooled[gcur * FF + f], acc);
                if (f == 0) atomicAdd(&d_cnt[gcur], cacc);
            }
            gcur = g; acc = 0.f; cacc = 0.f;
        }
        float v = fmaxf(af * d_y[(size_t)n * FF + f] + cf, 0.f);
        acc += v; cacc += 1.f;
    }
    if (gcur >= 0) {
        atomicAdd(&d_pooled[gcur * FF + f], acc);
        if (f == 0) atomicAdd(&d_cnt[gcur], cacc);
    }
}

__global__ void k_fc(const float* __restrict__ fw1, const float* __restrict__ fb1,
                     const float* __restrict__ fw2, const float* __restrict__ fb2,
                     float* __restrict__ out) {
    __shared__ float P[GG][FF];
    __shared__ float H[GG][128];
    int t = threadIdx.x;   // 128 threads
    for (int i = t; i < GG * FF; i += 128) {
        int g = i >> 6;
        float cc = d_cnt[g]; cc = (cc < 1.f) ? 1.f : cc;
        P[g][i & 63] = d_pooled[i] / cc;
    }
    __syncthreads();
    int j = t;  // hidden unit 0..127
    for (int g = 0; g < GG; g++) {
        float s = fb1[j];
        #pragma unroll 8
        for (int f = 0; f < FF; f++) s = fmaf(P[g][f], fw1[j * FF + f], s);
        H[g][j] = fmaxf(s, 0.f);
    }
    __syncthreads();
    for (int i = t; i < GG * 10; i += 128) {
        int g = i / 10, k = i % 10;
        float s = fb2[k];
        #pragma unroll 8
        for (int jj = 0; jj < 128; jj++) s = fmaf(H[g][jj], fw2[k * 128 + jj], s);
        out[i] = s;
    }
}

// ---------------- launch -----------------------------------------------------
extern "C" void kernel_launch(void* const* d_in, const int* in_sizes, int n_in,
                              void* d_out, int out_size) {
    const float* x   = (const float*)d_in[0];
    const int*   ei  = (const int*)d_in[1];
    const int*   bat = (const int*)d_in[2];
    const float* W1  = (const float*)d_in[3];
    const float* g1  = (const float*)d_in[5];
    const float* bt1 = (const float*)d_in[6];
    const float* W2  = (const float*)d_in[7];
    const float* g2  = (const float*)d_in[9];
    const float* bt2 = (const float*)d_in[10];
    const float* W3  = (const float*)d_in[11];
    const float* g3  = (const float*)d_in[13];
    const float* bt3 = (const float*)d_in[14];
    const float* W4  = (const float*)d_in[15];
    const float* g4  = (const float*)d_in[17];
    const float* bt4 = (const float*)d_in[18];
    const float* fw1 = (const float*)d_in[19];
    const float* fb1 = (const float*)d_in[20];
    const float* fw2 = (const float*)d_in[21];
    const float* fb2 = (const float*)d_in[22];
    float* out = (float*)d_out;

    int E_ = in_sizes[1] / 2;
    if (E_ > EE) E_ = EE;

    const int TB = 256;
    int nb_n  = (NN + TB - 1) / TB;
    int nb_e  = (E_ + TB - 1) / TB;
    int nb_nf = (NN * 16 + TB - 1) / TB;
    int nb_ef = (E_ * 16 + TB - 1) / TB;
    int nb_g  = (NN + 63) / 64;            // GEMM blocks (64 rows each)

    k_zero<<<16, TB>>>();
    k_init_deg<<<nb_n, TB>>>();
    k_deg<<<nb_e, TB>>>(ei, E_);
    k_dinv<<<nb_n, TB>>>(x);
    k_norm_s1<<<nb_e, TB>>>(ei, x, E_);
    k_stats_s<<<128, TB>>>();
    k_fin1<<<1, 64>>>(W1, g1, bt1);

    // layer 2
    k_gemm<true><<<nb_g, TB>>>(0, W2);
    k_selfloop<<<nb_nf, TB>>>();
    k_scatter<<<nb_ef, TB>>>(ei, E_);
    k_stats64<<<128, TB>>>(0);
    k_fin64<<<1, 64>>>(0, g2, bt2);

    // layer 3
    k_gemm<false><<<nb_g, TB>>>(1, W3);
    k_selfloop<<<nb_nf, TB>>>();
    k_scatter<<<nb_ef, TB>>>(ei, E_);
    k_stats64<<<128, TB>>>(1);
    k_fin64<<<1, 64>>>(1, g3, bt3);

    // layer 4
    k_gemm<false><<<nb_g, TB>>>(2, W4);
    k_selfloop<<<nb_nf, TB>>>();
    k_scatter<<<nb_ef, TB>>>(ei, E_);
    k_stats64<<<128, TB>>>(2);
    k_fin64<<<1, 64>>>(2, g4, bt4);

    // pool + head
    k_pool<<<(NN + 255) / 256, TB>>>(bat);
    k_fc<<<1, 128>>>(fw1, fb1, fw2, fb2, out);
}